// round 13
// baseline (speedup 1.0000x reference)
#include <cuda_runtime.h>
#include <cstdint>

#define N_IN   256
#define N_OUT  64
#define MAXN   100000
#define MAXE   1600000
#define SCAN_BS 512
#define MAX_SCAN_BLOCKS 256

// Scratch (allocation-free rule: __device__ globals). float4 => 16B aligned.
__device__ float4 g_bufA[(size_t)MAXN * N_OUT / 4];
__device__ float4 g_bufB[(size_t)MAXN * N_OUT / 4];
__device__ float  g_WT[N_OUT * N_IN];   // W transposed: WT[n][k]
__device__ int2   g_csr[MAXE];
__device__ int    g_deg[MAXN];
__device__ int    g_scanInc[MAXN];
__device__ int    g_rowptr[MAXN];
__device__ int    g_cursor[MAXN];
__device__ int    g_blockSums[MAX_SCAN_BLOCKS];
__device__ int    g_blockOff[MAX_SCAN_BLOCKS];
__device__ int    g_is64;

// ===================== dtype detect + CSR build =============================
__global__ void detect_dtype_kernel(const unsigned int* __restrict__ adj_words)
{
    unsigned int acc = 0;
    #pragma unroll
    for (int i = 1; i < 256; i += 2) acc |= adj_words[i];
    g_is64 = (acc == 0) ? 1 : 0;
}

__device__ __forceinline__ int load_idx(const void* adj, size_t i)
{
    return g_is64 ? (int)((const long long*)adj)[i] : ((const int*)adj)[i];
}

// Histogram: 2 edges/thread via one coalesced 16B (int64) / 8B (int32) row load.
__global__ void __launch_bounds__(256) histogram_kernel(const void* __restrict__ adj, int E)
{
    const int base = (blockIdx.x * 256 + threadIdx.x) * 2;
    if (base >= E) return;
    if (g_is64) {
        const ulonglong2 rr = ((const ulonglong2*)adj)[base >> 1];   // rows[base], rows[base+1]
        atomicAdd(&g_deg[(int)rr.x], 1);
        if (base + 1 < E) atomicAdd(&g_deg[(int)rr.y], 1);
    } else {
        const int2 rr = ((const int2*)adj)[base >> 1];
        atomicAdd(&g_deg[rr.x], 1);
        if (base + 1 < E) atomicAdd(&g_deg[rr.y], 1);
    }
}

__global__ void __launch_bounds__(SCAN_BS) scan1_kernel(int N)
{
    __shared__ int s[SCAN_BS];
    int i = blockIdx.x * SCAN_BS + threadIdx.x;
    int v = (i < N) ? g_deg[i] : 0;
    s[threadIdx.x] = v;
    __syncthreads();
    #pragma unroll
    for (int off = 1; off < SCAN_BS; off <<= 1) {
        int t = (threadIdx.x >= off) ? s[threadIdx.x - off] : 0;
        __syncthreads();
        s[threadIdx.x] += t;
        __syncthreads();
    }
    if (i < N) g_scanInc[i] = s[threadIdx.x];
    if (threadIdx.x == SCAN_BS - 1) g_blockSums[blockIdx.x] = s[SCAN_BS - 1];
}

__global__ void __launch_bounds__(MAX_SCAN_BLOCKS) scan2_kernel(int NB)
{
    __shared__ int s[MAX_SCAN_BLOCKS];
    int v = (threadIdx.x < NB) ? g_blockSums[threadIdx.x] : 0;
    s[threadIdx.x] = v;
    __syncthreads();
    #pragma unroll
    for (int off = 1; off < MAX_SCAN_BLOCKS; off <<= 1) {
        int t = (threadIdx.x >= off) ? s[threadIdx.x - off] : 0;
        __syncthreads();
        s[threadIdx.x] += t;
        __syncthreads();
    }
    g_blockOff[threadIdx.x] = s[threadIdx.x] - v;
}

__global__ void __launch_bounds__(256) scan3_kernel(int N)
{
    int i = blockIdx.x * 256 + threadIdx.x;
    if (i < N) {
        int excl = g_scanInc[i] - g_deg[i] + g_blockOff[i >> 9];
        g_rowptr[i] = excl;
        g_cursor[i] = excl;
    }
}

// Scatter: 2 edges/thread; rows via vector load, cols scalar (offset E may be odd-aligned).
__global__ void __launch_bounds__(256) scatter_kernel(
    const void* __restrict__ adj, const float* __restrict__ vals, int E)
{
    const int base = (blockIdx.x * 256 + threadIdx.x) * 2;
    if (base >= E) return;
    int r0, r1 = -1, c0, c1 = 0;
    if (g_is64) {
        const ulonglong2 rr = ((const ulonglong2*)adj)[base >> 1];
        const long long* a = (const long long*)adj;
        r0 = (int)rr.x;
        c0 = (int)a[(size_t)E + base];
        if (base + 1 < E) { r1 = (int)rr.y; c1 = (int)a[(size_t)E + base + 1]; }
    } else {
        const int2 rr = ((const int2*)adj)[base >> 1];
        const int* a = (const int*)adj;
        r0 = rr.x;
        c0 = a[E + base];
        if (base + 1 < E) { r1 = rr.y; c1 = a[E + base + 1]; }
    }
    const float2 vv = ((const float2*)vals)[base >> 1];   // 8B aligned (base even)
    int p0 = atomicAdd(&g_cursor[r0], 1);
    g_csr[p0] = make_int2(c0, __float_as_int(vv.x));
    if (r1 >= 0) {
        int p1 = atomicAdd(&g_cursor[r1], 1);
        g_csr[p1] = make_int2(c1, __float_as_int(vv.y));
    }
}

// W[256][64] -> WT[64][256]
__global__ void __launch_bounds__(256) transpose_w_kernel(const float* __restrict__ W)
{
    int i = blockIdx.x * 256 + threadIdx.x;
    int n = i >> 8, k = i & 255;
    g_WT[n * N_IN + k] = W[k * N_OUT + n];
}

// ===================== tf32 mma.sync GEMM + bias + ReLU =====================
__device__ __forceinline__ uint32_t f2tf32(float f)
{
    uint32_t u;
    asm("cvt.rna.tf32.f32 %0, %1;" : "=r"(u) : "f"(f));
    return u;
}

__device__ __forceinline__ void mma_tf32(float c[4], uint32_t a0, uint32_t a1,
                                         uint32_t a2, uint32_t a3,
                                         uint32_t b0, uint32_t b1)
{
    asm volatile(
        "mma.sync.aligned.m16n8k8.row.col.f32.tf32.tf32.f32 "
        "{%0,%1,%2,%3}, {%4,%5,%6,%7}, {%8,%9}, {%0,%1,%2,%3};"
        : "+f"(c[0]), "+f"(c[1]), "+f"(c[2]), "+f"(c[3])
        : "r"(a0), "r"(a1), "r"(a2), "r"(a3), "r"(b0), "r"(b1));
}

#define XS 36   // smem row stride (uint32)

__global__ void __launch_bounds__(256) gemm_tf32_kernel(
    const float* __restrict__ X, const float* __restrict__ bias,
    float* __restrict__ out, int NN)
{
    __shared__ uint32_t sX[128 * XS];
    __shared__ uint32_t sWT[64 * XS];

    const int tid  = threadIdx.x;
    const int wid  = tid >> 5;
    const int lid  = tid & 31;
    const int gid  = lid >> 2;
    const int tig  = lid & 3;
    const int row0 = blockIdx.x * 128;
    const int wrow = wid * 16;

    float c[8][4];
    #pragma unroll
    for (int nt = 0; nt < 8; nt++)
        #pragma unroll
        for (int j = 0; j < 4; j++) c[nt][j] = 0.f;

    for (int ch = 0; ch < 8; ch++) {
        const int k0 = ch * 32;
        #pragma unroll
        for (int i = tid; i < 1024; i += 256) {
            int r = i >> 3, q = i & 7;
            float4 v = make_float4(0.f, 0.f, 0.f, 0.f);
            if (row0 + r < NN)
                v = ((const float4*)(X + (size_t)(row0 + r) * N_IN + k0))[q];
            uint4 u = make_uint4(f2tf32(v.x), f2tf32(v.y), f2tf32(v.z), f2tf32(v.w));
            *(uint4*)(sX + r * XS + q * 4) = u;
        }
        #pragma unroll
        for (int i = tid; i < 512; i += 256) {
            int n = i >> 3, q = i & 7;
            float4 v = ((const float4*)(g_WT + (size_t)n * N_IN + k0))[q];
            uint4 u = make_uint4(f2tf32(v.x), f2tf32(v.y), f2tf32(v.z), f2tf32(v.w));
            *(uint4*)(sWT + n * XS + q * 4) = u;
        }
        __syncthreads();

        #pragma unroll
        for (int ks = 0; ks < 4; ks++) {
            const int kb = ks * 8;
            uint32_t a0 = sX[(wrow + gid)     * XS + kb + tig];
            uint32_t a1 = sX[(wrow + gid + 8) * XS + kb + tig];
            uint32_t a2 = sX[(wrow + gid)     * XS + kb + tig + 4];
            uint32_t a3 = sX[(wrow + gid + 8) * XS + kb + tig + 4];
            #pragma unroll
            for (int nt = 0; nt < 8; nt++) {
                uint32_t b0 = sWT[(nt * 8 + gid) * XS + kb + tig];
                uint32_t b1 = sWT[(nt * 8 + gid) * XS + kb + tig + 4];
                mma_tf32(c[nt], a0, a1, a2, a3, b0, b1);
            }
        }
        __syncthreads();
    }

    const int row_lo = row0 + wrow + gid;
    const int row_hi = row_lo + 8;
    #pragma unroll
    for (int nt = 0; nt < 8; nt++) {
        const int col = nt * 8 + tig * 2;
        const float b0 = __ldg(bias + col);
        const float b1 = __ldg(bias + col + 1);
        if (row_lo < NN) {
            float2 o = make_float2(fmaxf(c[nt][0] + b0, 0.f),
                                   fmaxf(c[nt][1] + b1, 0.f));
            *(float2*)(out + (size_t)row_lo * N_OUT + col) = o;
        }
        if (row_hi < NN) {
            float2 o = make_float2(fmaxf(c[nt][2] + b0, 0.f),
                                   fmaxf(c[nt][3] + b1, 0.f));
            *(float2*)(out + (size_t)row_hi * N_OUT + col) = o;
        }
    }
}

// ===================== CSR SpMM (atomic-free, MLP=8) ========================
__global__ void __launch_bounds__(256) spmm_csr_kernel(
    const float4* __restrict__ src, float4* __restrict__ dst, int N)
{
    const int ch  = threadIdx.x & 15;
    const int grp = threadIdx.x >> 4;
    const int row = blockIdx.x * 16 + grp;
    if (row >= N) return;

    int e   = g_rowptr[row];
    int end = g_cursor[row];

    float4 acc = make_float4(0.f, 0.f, 0.f, 0.f);

    for (; e + 8 <= end; e += 8) {
        int2 p[8];
        #pragma unroll
        for (int j = 0; j < 8; j++) p[j] = g_csr[e + j];
        float4 b[8];
        #pragma unroll
        for (int j = 0; j < 8; j++)
            b[j] = __ldg(src + (size_t)p[j].x * (N_OUT / 4) + ch);
        #pragma unroll
        for (int j = 0; j < 8; j++) {
            float v = __int_as_float(p[j].y);
            acc.x += v * b[j].x; acc.y += v * b[j].y;
            acc.z += v * b[j].z; acc.w += v * b[j].w;
        }
    }
    for (; e + 4 <= end; e += 4) {
        int2 p[4];
        #pragma unroll
        for (int j = 0; j < 4; j++) p[j] = g_csr[e + j];
        float4 b[4];
        #pragma unroll
        for (int j = 0; j < 4; j++)
            b[j] = __ldg(src + (size_t)p[j].x * (N_OUT / 4) + ch);
        #pragma unroll
        for (int j = 0; j < 4; j++) {
            float v = __int_as_float(p[j].y);
            acc.x += v * b[j].x; acc.y += v * b[j].y;
            acc.z += v * b[j].z; acc.w += v * b[j].w;
        }
    }
    for (; e < end; e++) {
        int2 p = g_csr[e];
        float4 b = __ldg(src + (size_t)p.x * (N_OUT / 4) + ch);
        float v = __int_as_float(p.y);
        acc.x += v * b.x; acc.y += v * b.y; acc.z += v * b.z; acc.w += v * b.w;
    }

    dst[(size_t)row * (N_OUT / 4) + ch] = acc;
}

// ===================== launch ===============================================
// Main stream: detect -> memset -> histogram -> scan x3 -> scatter --\
// Side  s2:   transpose -> GEMM --------------------------------- join -> spmm x3
extern "C" void kernel_launch(void* const* d_in, const int* in_sizes, int n_in,
                              void* d_out, int out_size)
{
    const void*  adj  = d_in[0];
    const float* vals = (const float*)d_in[1];
    const float* X    = (const float*)d_in[2];
    const float* W    = (const float*)d_in[3];
    const float* bias = (const float*)d_in[4];
    float4*      out  = (float4*)d_out;

    const int E = in_sizes[0] / 2;
    const int N = in_sizes[2] / N_IN;

    float4* bufA = nullptr;
    float4* bufB = nullptr;
    int*    degp = nullptr;
    cudaGetSymbolAddress((void**)&bufA, g_bufA);
    cudaGetSymbolAddress((void**)&bufB, g_bufB);
    cudaGetSymbolAddress((void**)&degp, g_deg);

    // One-time host objects (no device memory involved).
    static cudaStream_t s2 = nullptr;
    static cudaEvent_t evFork = nullptr, evJoin = nullptr;
    if (!s2) {
        cudaStreamCreate(&s2);
        cudaEventCreateWithFlags(&evFork, cudaEventDisableTiming);
        cudaEventCreateWithFlags(&evJoin, cudaEventDisableTiming);
    }

    // Fork side branch off stream 0.
    cudaEventRecord(evFork, 0);
    cudaStreamWaitEvent(s2, evFork, 0);

    // Side branch: W transpose -> tf32 GEMM -> bufA
    transpose_w_kernel<<<(N_IN * N_OUT + 255) / 256, 256, 0, s2>>>(W);
    gemm_tf32_kernel<<<(N + 127) / 128, 256, 0, s2>>>(X, bias, (float*)bufA, N);
    cudaEventRecord(evJoin, s2);

    // Main branch: CSR build
    detect_dtype_kernel<<<1, 1>>>((const unsigned int*)adj);
    cudaMemsetAsync(degp, 0, (size_t)N * sizeof(int), 0);
    const int eb2 = (E + 511) / 512;   // 2 edges/thread blocks
    histogram_kernel<<<eb2, 256>>>(adj, E);
    const int NB = (N + SCAN_BS - 1) / SCAN_BS;
    scan1_kernel<<<NB, SCAN_BS>>>(N);
    scan2_kernel<<<1, MAX_SCAN_BLOCKS>>>(NB);
    scan3_kernel<<<(N + 255) / 256, 256>>>(N);
    scatter_kernel<<<eb2, 256>>>(adj, vals, E);

    // Join: SpMM needs both bufA (GEMM) and CSR.
    cudaStreamWaitEvent(0, evJoin, 0);

    const int spmm_blocks = (N + 15) / 16;
    spmm_csr_kernel<<<spmm_blocks, 256>>>(bufA, bufB, N);
    spmm_csr_kernel<<<spmm_blocks, 256>>>(bufB, bufA, N);
    spmm_csr_kernel<<<spmm_blocks, 256>>>(bufA, out, N);
}

// round 14
// speedup vs baseline: 1.1254x; 1.1254x over previous
#include <cuda_runtime.h>
#include <cuda_fp16.h>
#include <cstdint>

#define N_IN   256
#define N_OUT  64
#define MAXN   100000
#define MAXE   1600000
#define SCAN_BS 512
#define MAX_SCAN_BLOCKS 256

// Scratch (allocation-free rule: __device__ globals).
// Feature buffers in fp16: 64 ch = 32 half2 = 16 uint2 (128B) per row.
__device__ uint2  g_hA[(size_t)MAXN * 16];
__device__ uint2  g_hB[(size_t)MAXN * 16];
__device__ int2   g_csr[MAXE];
__device__ float  g_WT[N_OUT * N_IN];   // W transposed: WT[n][k]
__device__ int    g_deg[MAXN];
__device__ int    g_scanInc[MAXN];
__device__ int    g_rowptr[MAXN];
__device__ int    g_cursor[MAXN];
__device__ int    g_blockSums[MAX_SCAN_BLOCKS];
__device__ int    g_blockOff[MAX_SCAN_BLOCKS];
__device__ int    g_is64;

// ===================== dtype detect + CSR build =============================
__global__ void detect_dtype_kernel(const unsigned int* __restrict__ adj_words)
{
    unsigned int acc = 0;
    #pragma unroll
    for (int i = 1; i < 256; i += 2) acc |= adj_words[i];
    g_is64 = (acc == 0) ? 1 : 0;
}

// Histogram: 2 edges/thread via one coalesced row load.
__global__ void __launch_bounds__(256) histogram_kernel(const void* __restrict__ adj, int E)
{
    const int base = (blockIdx.x * 256 + threadIdx.x) * 2;
    if (base >= E) return;
    if (g_is64) {
        const ulonglong2 rr = ((const ulonglong2*)adj)[base >> 1];
        atomicAdd(&g_deg[(int)rr.x], 1);
        if (base + 1 < E) atomicAdd(&g_deg[(int)rr.y], 1);
    } else {
        const int2 rr = ((const int2*)adj)[base >> 1];
        atomicAdd(&g_deg[rr.x], 1);
        if (base + 1 < E) atomicAdd(&g_deg[rr.y], 1);
    }
}

__global__ void __launch_bounds__(SCAN_BS) scan1_kernel(int N)
{
    __shared__ int s[SCAN_BS];
    int i = blockIdx.x * SCAN_BS + threadIdx.x;
    int v = (i < N) ? g_deg[i] : 0;
    s[threadIdx.x] = v;
    __syncthreads();
    #pragma unroll
    for (int off = 1; off < SCAN_BS; off <<= 1) {
        int t = (threadIdx.x >= off) ? s[threadIdx.x - off] : 0;
        __syncthreads();
        s[threadIdx.x] += t;
        __syncthreads();
    }
    if (i < N) g_scanInc[i] = s[threadIdx.x];
    if (threadIdx.x == SCAN_BS - 1) g_blockSums[blockIdx.x] = s[SCAN_BS - 1];
}

__global__ void __launch_bounds__(MAX_SCAN_BLOCKS) scan2_kernel(int NB)
{
    __shared__ int s[MAX_SCAN_BLOCKS];
    int v = (threadIdx.x < NB) ? g_blockSums[threadIdx.x] : 0;
    s[threadIdx.x] = v;
    __syncthreads();
    #pragma unroll
    for (int off = 1; off < MAX_SCAN_BLOCKS; off <<= 1) {
        int t = (threadIdx.x >= off) ? s[threadIdx.x - off] : 0;
        __syncthreads();
        s[threadIdx.x] += t;
        __syncthreads();
    }
    g_blockOff[threadIdx.x] = s[threadIdx.x] - v;
}

__global__ void __launch_bounds__(256) scan3_kernel(int N)
{
    int i = blockIdx.x * 256 + threadIdx.x;
    if (i < N) {
        int excl = g_scanInc[i] - g_deg[i] + g_blockOff[i >> 9];
        g_rowptr[i] = excl;
        g_cursor[i] = excl;
    }
}

// Scatter: 2 edges/thread; rows vector load, cols scalar.
__global__ void __launch_bounds__(256) scatter_kernel(
    const void* __restrict__ adj, const float* __restrict__ vals, int E)
{
    const int base = (blockIdx.x * 256 + threadIdx.x) * 2;
    if (base >= E) return;
    int r0, r1 = -1, c0, c1 = 0;
    if (g_is64) {
        const ulonglong2 rr = ((const ulonglong2*)adj)[base >> 1];
        const long long* a = (const long long*)adj;
        r0 = (int)rr.x;
        c0 = (int)a[(size_t)E + base];
        if (base + 1 < E) { r1 = (int)rr.y; c1 = (int)a[(size_t)E + base + 1]; }
    } else {
        const int2 rr = ((const int2*)adj)[base >> 1];
        const int* a = (const int*)adj;
        r0 = rr.x;
        c0 = a[E + base];
        if (base + 1 < E) { r1 = rr.y; c1 = a[E + base + 1]; }
    }
    const float2 vv = ((const float2*)vals)[base >> 1];
    int p0 = atomicAdd(&g_cursor[r0], 1);
    g_csr[p0] = make_int2(c0, __float_as_int(vv.x));
    if (r1 >= 0) {
        int p1 = atomicAdd(&g_cursor[r1], 1);
        g_csr[p1] = make_int2(c1, __float_as_int(vv.y));
    }
}

// W[256][64] -> WT[64][256]
__global__ void __launch_bounds__(256) transpose_w_kernel(const float* __restrict__ W)
{
    int i = blockIdx.x * 256 + threadIdx.x;
    int n = i >> 8, k = i & 255;
    g_WT[n * N_IN + k] = W[k * N_OUT + n];
}

// ===================== tf32 mma.sync GEMM + bias + ReLU -> fp16 =============
__device__ __forceinline__ uint32_t f2tf32(float f)
{
    uint32_t u;
    asm("cvt.rna.tf32.f32 %0, %1;" : "=r"(u) : "f"(f));
    return u;
}

__device__ __forceinline__ void mma_tf32(float c[4], uint32_t a0, uint32_t a1,
                                         uint32_t a2, uint32_t a3,
                                         uint32_t b0, uint32_t b1)
{
    asm volatile(
        "mma.sync.aligned.m16n8k8.row.col.f32.tf32.tf32.f32 "
        "{%0,%1,%2,%3}, {%4,%5,%6,%7}, {%8,%9}, {%0,%1,%2,%3};"
        : "+f"(c[0]), "+f"(c[1]), "+f"(c[2]), "+f"(c[3])
        : "r"(a0), "r"(a1), "r"(a2), "r"(a3), "r"(b0), "r"(b1));
}

#define XS 36   // smem row stride (uint32)

__global__ void __launch_bounds__(256) gemm_tf32_kernel(
    const float* __restrict__ X, const float* __restrict__ bias,
    __half* __restrict__ out, int NN)
{
    __shared__ uint32_t sX[128 * XS];
    __shared__ uint32_t sWT[64 * XS];

    const int tid  = threadIdx.x;
    const int wid  = tid >> 5;
    const int lid  = tid & 31;
    const int gid  = lid >> 2;
    const int tig  = lid & 3;
    const int row0 = blockIdx.x * 128;
    const int wrow = wid * 16;

    float c[8][4];
    #pragma unroll
    for (int nt = 0; nt < 8; nt++)
        #pragma unroll
        for (int j = 0; j < 4; j++) c[nt][j] = 0.f;

    for (int ch = 0; ch < 8; ch++) {
        const int k0 = ch * 32;
        #pragma unroll
        for (int i = tid; i < 1024; i += 256) {
            int r = i >> 3, q = i & 7;
            float4 v = make_float4(0.f, 0.f, 0.f, 0.f);
            if (row0 + r < NN)
                v = ((const float4*)(X + (size_t)(row0 + r) * N_IN + k0))[q];
            uint4 u = make_uint4(f2tf32(v.x), f2tf32(v.y), f2tf32(v.z), f2tf32(v.w));
            *(uint4*)(sX + r * XS + q * 4) = u;
        }
        #pragma unroll
        for (int i = tid; i < 512; i += 256) {
            int n = i >> 3, q = i & 7;
            float4 v = ((const float4*)(g_WT + (size_t)n * N_IN + k0))[q];
            uint4 u = make_uint4(f2tf32(v.x), f2tf32(v.y), f2tf32(v.z), f2tf32(v.w));
            *(uint4*)(sWT + n * XS + q * 4) = u;
        }
        __syncthreads();

        #pragma unroll
        for (int ks = 0; ks < 4; ks++) {
            const int kb = ks * 8;
            uint32_t a0 = sX[(wrow + gid)     * XS + kb + tig];
            uint32_t a1 = sX[(wrow + gid + 8) * XS + kb + tig];
            uint32_t a2 = sX[(wrow + gid)     * XS + kb + tig + 4];
            uint32_t a3 = sX[(wrow + gid + 8) * XS + kb + tig + 4];
            #pragma unroll
            for (int nt = 0; nt < 8; nt++) {
                uint32_t b0 = sWT[(nt * 8 + gid) * XS + kb + tig];
                uint32_t b1 = sWT[(nt * 8 + gid) * XS + kb + tig + 4];
                mma_tf32(c[nt], a0, a1, a2, a3, b0, b1);
            }
        }
        __syncthreads();
    }

    const int row_lo = row0 + wrow + gid;
    const int row_hi = row_lo + 8;
    #pragma unroll
    for (int nt = 0; nt < 8; nt++) {
        const int col = nt * 8 + tig * 2;
        const float b0 = __ldg(bias + col);
        const float b1 = __ldg(bias + col + 1);
        if (row_lo < NN) {
            __half2 h = __floats2half2_rn(fmaxf(c[nt][0] + b0, 0.f),
                                          fmaxf(c[nt][1] + b1, 0.f));
            *(__half2*)(out + (size_t)row_lo * N_OUT + col) = h;
        }
        if (row_hi < NN) {
            __half2 h = __floats2half2_rn(fmaxf(c[nt][2] + b0, 0.f),
                                          fmaxf(c[nt][3] + b1, 0.f));
            *(__half2*)(out + (size_t)row_hi * N_OUT + col) = h;
        }
    }
}

// ===================== CSR SpMM (fp16 src, fp32 accum) ======================
// 16 threads/row; thread ch handles channels [4ch, 4ch+4): one uint2 (4 halves).
__device__ __forceinline__ void gather_fma(float4& acc, float v, uint2 g)
{
    __half2 h0 = *(__half2*)&g.x;
    __half2 h1 = *(__half2*)&g.y;
    float2 f0 = __half22float2(h0);
    float2 f1 = __half22float2(h1);
    acc.x += v * f0.x; acc.y += v * f0.y;
    acc.z += v * f1.x; acc.w += v * f1.y;
}

__device__ __forceinline__ float4 spmm_row_accum(
    const uint2* __restrict__ src, int row, int ch)
{
    int e   = g_rowptr[row];
    int end = g_cursor[row];
    float4 acc = make_float4(0.f, 0.f, 0.f, 0.f);

    for (; e + 8 <= end; e += 8) {
        int2 p[8];
        #pragma unroll
        for (int j = 0; j < 8; j++) p[j] = g_csr[e + j];
        uint2 b[8];
        #pragma unroll
        for (int j = 0; j < 8; j++)
            b[j] = __ldg(src + (size_t)p[j].x * 16 + ch);
        #pragma unroll
        for (int j = 0; j < 8; j++)
            gather_fma(acc, __int_as_float(p[j].y), b[j]);
    }
    for (; e + 4 <= end; e += 4) {
        int2 p[4];
        #pragma unroll
        for (int j = 0; j < 4; j++) p[j] = g_csr[e + j];
        uint2 b[4];
        #pragma unroll
        for (int j = 0; j < 4; j++)
            b[j] = __ldg(src + (size_t)p[j].x * 16 + ch);
        #pragma unroll
        for (int j = 0; j < 4; j++)
            gather_fma(acc, __int_as_float(p[j].y), b[j]);
    }
    for (; e < end; e++) {
        int2 p = g_csr[e];
        uint2 b = __ldg(src + (size_t)p.x * 16 + ch);
        gather_fma(acc, __int_as_float(p.y), b);
    }
    return acc;
}

// Hops 1,2: half -> half
__global__ void __launch_bounds__(256) spmm_h2h_kernel(
    const uint2* __restrict__ src, uint2* __restrict__ dst, int N)
{
    const int ch  = threadIdx.x & 15;
    const int row = blockIdx.x * 16 + (threadIdx.x >> 4);
    if (row >= N) return;
    float4 acc = spmm_row_accum(src, row, ch);
    __half2 lo = __floats2half2_rn(acc.x, acc.y);
    __half2 hi = __floats2half2_rn(acc.z, acc.w);
    uint2 o;
    o.x = *(uint32_t*)&lo;
    o.y = *(uint32_t*)&hi;
    dst[(size_t)row * 16 + ch] = o;
}

// Hop 3: half -> float (d_out)
__global__ void __launch_bounds__(256) spmm_h2f_kernel(
    const uint2* __restrict__ src, float4* __restrict__ dst, int N)
{
    const int ch  = threadIdx.x & 15;
    const int row = blockIdx.x * 16 + (threadIdx.x >> 4);
    if (row >= N) return;
    float4 acc = spmm_row_accum(src, row, ch);
    dst[(size_t)row * 16 + ch] = acc;
}

// ===================== launch ===============================================
// Main stream: detect -> memset -> histogram -> scan x3 -> scatter --\
// Side  s2:   transpose -> GEMM --------------------------------- join -> spmm x3
extern "C" void kernel_launch(void* const* d_in, const int* in_sizes, int n_in,
                              void* d_out, int out_size)
{
    const void*  adj  = d_in[0];
    const float* vals = (const float*)d_in[1];
    const float* X    = (const float*)d_in[2];
    const float* W    = (const float*)d_in[3];
    const float* bias = (const float*)d_in[4];
    float4*      out  = (float4*)d_out;

    const int E = in_sizes[0] / 2;
    const int N = in_sizes[2] / N_IN;

    uint2* hA = nullptr;
    uint2* hB = nullptr;
    int*   degp = nullptr;
    cudaGetSymbolAddress((void**)&hA, g_hA);
    cudaGetSymbolAddress((void**)&hB, g_hB);
    cudaGetSymbolAddress((void**)&degp, g_deg);

    // One-time host objects (no device memory involved).
    static cudaStream_t s2 = nullptr;
    static cudaEvent_t evFork = nullptr, evJoin = nullptr;
    if (!s2) {
        cudaStreamCreate(&s2);
        cudaEventCreateWithFlags(&evFork, cudaEventDisableTiming);
        cudaEventCreateWithFlags(&evJoin, cudaEventDisableTiming);
    }

    // Fork side branch off stream 0.
    cudaEventRecord(evFork, 0);
    cudaStreamWaitEvent(s2, evFork, 0);

    // Side branch: W transpose -> tf32 GEMM -> hA (fp16)
    transpose_w_kernel<<<(N_IN * N_OUT + 255) / 256, 256, 0, s2>>>(W);
    gemm_tf32_kernel<<<(N + 127) / 128, 256, 0, s2>>>(X, bias, (__half*)hA, N);
    cudaEventRecord(evJoin, s2);

    // Main branch: CSR build
    detect_dtype_kernel<<<1, 1>>>((const unsigned int*)adj);
    cudaMemsetAsync(degp, 0, (size_t)N * sizeof(int), 0);
    const int eb2 = (E + 511) / 512;
    histogram_kernel<<<eb2, 256>>>(adj, E);
    const int NB = (N + SCAN_BS - 1) / SCAN_BS;
    scan1_kernel<<<NB, SCAN_BS>>>(N);
    scan2_kernel<<<1, MAX_SCAN_BLOCKS>>>(NB);
    scan3_kernel<<<(N + 255) / 256, 256>>>(N);
    scatter_kernel<<<eb2, 256>>>(adj, vals, E);

    // Join: SpMM needs both hA (GEMM) and CSR.
    cudaStreamWaitEvent(0, evJoin, 0);

    const int spmm_blocks = (N + 15) / 16;
    spmm_h2h_kernel<<<spmm_blocks, 256>>>(hA, hB, N);
    spmm_h2h_kernel<<<spmm_blocks, 256>>>(hB, hA, N);
    spmm_h2f_kernel<<<spmm_blocks, 256>>>(hA, out, N);
}

// round 17
// speedup vs baseline: 1.1584x; 1.0293x over previous
#include <cuda_runtime.h>
#include <cuda_fp16.h>
#include <cstdint>

#define N_IN   256
#define N_OUT  64
#define MAXN   100000
#define MAXE   1600000
#define SCAN_BS 512
#define MAX_SCAN_BLOCKS 256

// Scratch (allocation-free rule: __device__ globals).
// Feature buffers in fp16: 64 ch = 8 uint4 (128B) per row.
__device__ uint4  g_hA[(size_t)MAXN * 8];
__device__ uint4  g_hB[(size_t)MAXN * 8];
__device__ int2   g_csr[MAXE];
__device__ float  g_WT[N_OUT * N_IN];   // W transposed: WT[n][k]
__device__ int    g_deg[MAXN];
__device__ int    g_scanInc[MAXN];
__device__ int    g_rowptr[MAXN];
__device__ int    g_cursor[MAXN];
__device__ int    g_blockSums[MAX_SCAN_BLOCKS];
__device__ int    g_blockOff[MAX_SCAN_BLOCKS];

// ===================== local dtype detect (per-block, no extra kernel) ======
// LE int64 indices < 2^32 => odd 32-bit words of the rows array are all zero.
// For int32 data those words are random node ids; P(32 words all zero) ~ 1e-160.
__device__ __forceinline__ int detect_is64_block(const void* adj)
{
    __shared__ int s_is64;
    if (threadIdx.x < 32) {
        const unsigned int* w = (const unsigned int*)adj;
        unsigned int v = w[threadIdx.x * 2 + 1];
        int any = __any_sync(0xFFFFFFFFu, v != 0);
        if (threadIdx.x == 0) s_is64 = !any;
    }
    __syncthreads();
    return s_is64;
}

// ===================== CSR build =============================================
// Histogram: 2 edges/thread via one coalesced row load.
__global__ void __launch_bounds__(256) histogram_kernel(const void* __restrict__ adj, int E)
{
    const int is64 = detect_is64_block(adj);
    const int base = (blockIdx.x * 256 + threadIdx.x) * 2;
    if (base >= E) return;
    if (is64) {
        const ulonglong2 rr = ((const ulonglong2*)adj)[base >> 1];
        atomicAdd(&g_deg[(int)rr.x], 1);
        if (base + 1 < E) atomicAdd(&g_deg[(int)rr.y], 1);
    } else {
        const int2 rr = ((const int2*)adj)[base >> 1];
        atomicAdd(&g_deg[rr.x], 1);
        if (base + 1 < E) atomicAdd(&g_deg[rr.y], 1);
    }
}

__global__ void __launch_bounds__(SCAN_BS) scan1_kernel(int N)
{
    __shared__ int s[SCAN_BS];
    int i = blockIdx.x * SCAN_BS + threadIdx.x;
    int v = (i < N) ? g_deg[i] : 0;
    s[threadIdx.x] = v;
    __syncthreads();
    #pragma unroll
    for (int off = 1; off < SCAN_BS; off <<= 1) {
        int t = (threadIdx.x >= off) ? s[threadIdx.x - off] : 0;
        __syncthreads();
        s[threadIdx.x] += t;
        __syncthreads();
    }
    if (i < N) g_scanInc[i] = s[threadIdx.x];
    if (threadIdx.x == SCAN_BS - 1) g_blockSums[blockIdx.x] = s[SCAN_BS - 1];
}

__global__ void __launch_bounds__(MAX_SCAN_BLOCKS) scan2_kernel(int NB)
{
    __shared__ int s[MAX_SCAN_BLOCKS];
    int v = (threadIdx.x < NB) ? g_blockSums[threadIdx.x] : 0;
    s[threadIdx.x] = v;
    __syncthreads();
    #pragma unroll
    for (int off = 1; off < MAX_SCAN_BLOCKS; off <<= 1) {
        int t = (threadIdx.x >= off) ? s[threadIdx.x - off] : 0;
        __syncthreads();
        s[threadIdx.x] += t;
        __syncthreads();
    }
    g_blockOff[threadIdx.x] = s[threadIdx.x] - v;
}

__global__ void __launch_bounds__(256) scan3_kernel(int N)
{
    int i = blockIdx.x * 256 + threadIdx.x;
    if (i < N) {
        int excl = g_scanInc[i] - g_deg[i] + g_blockOff[i >> 9];
        g_rowptr[i] = excl;
        g_cursor[i] = excl;
    }
}

// Scatter: 2 edges/thread; rows vector load, cols scalar.
__global__ void __launch_bounds__(256) scatter_kernel(
    const void* __restrict__ adj, const float* __restrict__ vals, int E)
{
    const int is64 = detect_is64_block(adj);
    const int base = (blockIdx.x * 256 + threadIdx.x) * 2;
    if (base >= E) return;
    int r0, r1 = -1, c0, c1 = 0;
    if (is64) {
        const ulonglong2 rr = ((const ulonglong2*)adj)[base >> 1];
        const long long* a = (const long long*)adj;
        r0 = (int)rr.x;
        c0 = (int)a[(size_t)E + base];
        if (base + 1 < E) { r1 = (int)rr.y; c1 = (int)a[(size_t)E + base + 1]; }
    } else {
        const int2 rr = ((const int2*)adj)[base >> 1];
        const int* a = (const int*)adj;
        r0 = rr.x;
        c0 = a[E + base];
        if (base + 1 < E) { r1 = rr.y; c1 = a[E + base + 1]; }
    }
    const float2 vv = ((const float2*)vals)[base >> 1];
    int p0 = atomicAdd(&g_cursor[r0], 1);
    g_csr[p0] = make_int2(c0, __float_as_int(vv.x));
    if (r1 >= 0) {
        int p1 = atomicAdd(&g_cursor[r1], 1);
        g_csr[p1] = make_int2(c1, __float_as_int(vv.y));
    }
}

// W[256][64] -> WT[64][256]
__global__ void __launch_bounds__(256) transpose_w_kernel(const float* __restrict__ W)
{
    int i = blockIdx.x * 256 + threadIdx.x;
    int n = i >> 8, k = i & 255;
    g_WT[n * N_IN + k] = W[k * N_OUT + n];
}

// ===================== tf32 mma.sync GEMM + bias + ReLU -> fp16 =============
__device__ __forceinline__ uint32_t f2tf32(float f)
{
    uint32_t u;
    asm("cvt.rna.tf32.f32 %0, %1;" : "=r"(u) : "f"(f));
    return u;
}

__device__ __forceinline__ void mma_tf32(float c[4], uint32_t a0, uint32_t a1,
                                         uint32_t a2, uint32_t a3,
                                         uint32_t b0, uint32_t b1)
{
    asm volatile(
        "mma.sync.aligned.m16n8k8.row.col.f32.tf32.tf32.f32 "
        "{%0,%1,%2,%3}, {%4,%5,%6,%7}, {%8,%9}, {%0,%1,%2,%3};"
        : "+f"(c[0]), "+f"(c[1]), "+f"(c[2]), "+f"(c[3])
        : "r"(a0), "r"(a1), "r"(a2), "r"(a3), "r"(b0), "r"(b1));
}

#define XS 36   // smem row stride (uint32)

__global__ void __launch_bounds__(256) gemm_tf32_kernel(
    const float* __restrict__ X, const float* __restrict__ bias,
    __half* __restrict__ out, int NN)
{
    __shared__ uint32_t sX[128 * XS];
    __shared__ uint32_t sWT[64 * XS];

    const int tid  = threadIdx.x;
    const int wid  = tid >> 5;
    const int lid  = tid & 31;
    const int gid  = lid >> 2;
    const int tig  = lid & 3;
    const int row0 = blockIdx.x * 128;
    const int wrow = wid * 16;

    float c[8][4];
    #pragma unroll
    for (int nt = 0; nt < 8; nt++)
        #pragma unroll
        for (int j = 0; j < 4; j++) c[nt][j] = 0.f;

    for (int ch = 0; ch < 8; ch++) {
        const int k0 = ch * 32;
        #pragma unroll
        for (int i = tid; i < 1024; i += 256) {
            int r = i >> 3, q = i & 7;
            float4 v = make_float4(0.f, 0.f, 0.f, 0.f);
            if (row0 + r < NN)
                v = ((const float4*)(X + (size_t)(row0 + r) * N_IN + k0))[q];
            uint4 u = make_uint4(f2tf32(v.x), f2tf32(v.y), f2tf32(v.z), f2tf32(v.w));
            *(uint4*)(sX + r * XS + q * 4) = u;
        }
        #pragma unroll
        for (int i = tid; i < 512; i += 256) {
            int n = i >> 3, q = i & 7;
            float4 v = ((const float4*)(g_WT + (size_t)n * N_IN + k0))[q];
            uint4 u = make_uint4(f2tf32(v.x), f2tf32(v.y), f2tf32(v.z), f2tf32(v.w));
            *(uint4*)(sWT + n * XS + q * 4) = u;
        }
        __syncthreads();

        #pragma unroll
        for (int ks = 0; ks < 4; ks++) {
            const int kb = ks * 8;
            uint32_t a0 = sX[(wrow + gid)     * XS + kb + tig];
            uint32_t a1 = sX[(wrow + gid + 8) * XS + kb + tig];
            uint32_t a2 = sX[(wrow + gid)     * XS + kb + tig + 4];
            uint32_t a3 = sX[(wrow + gid + 8) * XS + kb + tig + 4];
            #pragma unroll
            for (int nt = 0; nt < 8; nt++) {
                uint32_t b0 = sWT[(nt * 8 + gid) * XS + kb + tig];
                uint32_t b1 = sWT[(nt * 8 + gid) * XS + kb + tig + 4];
                mma_tf32(c[nt], a0, a1, a2, a3, b0, b1);
            }
        }
        __syncthreads();
    }

    const int row_lo = row0 + wrow + gid;
    const int row_hi = row_lo + 8;
    #pragma unroll
    for (int nt = 0; nt < 8; nt++) {
        const int col = nt * 8 + tig * 2;
        const float b0 = __ldg(bias + col);
        const float b1 = __ldg(bias + col + 1);
        if (row_lo < NN) {
            __half2 h = __floats2half2_rn(fmaxf(c[nt][0] + b0, 0.f),
                                          fmaxf(c[nt][1] + b1, 0.f));
            *(__half2*)(out + (size_t)row_lo * N_OUT + col) = h;
        }
        if (row_hi < NN) {
            __half2 h = __floats2half2_rn(fmaxf(c[nt][2] + b0, 0.f),
                                          fmaxf(c[nt][3] + b1, 0.f));
            *(__half2*)(out + (size_t)row_hi * N_OUT + col) = h;
        }
    }
}

// ===================== CSR SpMM (fp16 src, fp32 accum) ======================
// 8 threads/row; thread ch handles channels [8ch, 8ch+8): one uint4 (8 halves).
struct Acc8 { float f[8]; };

__device__ __forceinline__ void gather_fma8(Acc8& acc, float v, uint4 g)
{
    float2 f0 = __half22float2(*(__half2*)&g.x);
    float2 f1 = __half22float2(*(__half2*)&g.y);
    float2 f2 = __half22float2(*(__half2*)&g.z);
    float2 f3 = __half22float2(*(__half2*)&g.w);
    acc.f[0] += v * f0.x; acc.f[1] += v * f0.y;
    acc.f[2] += v * f1.x; acc.f[3] += v * f1.y;
    acc.f[4] += v * f2.x; acc.f[5] += v * f2.y;
    acc.f[6] += v * f3.x; acc.f[7] += v * f3.y;
}

__device__ __forceinline__ Acc8 spmm_row_accum(
    const uint4* __restrict__ src, int row, int ch)
{
    int e   = g_rowptr[row];
    int end = g_cursor[row];
    Acc8 acc;
    #pragma unroll
    for (int j = 0; j < 8; j++) acc.f[j] = 0.f;

    for (; e + 8 <= end; e += 8) {
        int2 p[8];
        #pragma unroll
        for (int j = 0; j < 8; j++) p[j] = g_csr[e + j];
        uint4 b[8];
        #pragma unroll
        for (int j = 0; j < 8; j++)
            b[j] = __ldg(src + (size_t)p[j].x * 8 + ch);
        #pragma unroll
        for (int j = 0; j < 8; j++)
            gather_fma8(acc, __int_as_float(p[j].y), b[j]);
    }
    for (; e + 4 <= end; e += 4) {
        int2 p[4];
        #pragma unroll
        for (int j = 0; j < 4; j++) p[j] = g_csr[e + j];
        uint4 b[4];
        #pragma unroll
        for (int j = 0; j < 4; j++)
            b[j] = __ldg(src + (size_t)p[j].x * 8 + ch);
        #pragma unroll
        for (int j = 0; j < 4; j++)
            gather_fma8(acc, __int_as_float(p[j].y), b[j]);
    }
    for (; e < end; e++) {
        int2 p = g_csr[e];
        uint4 b = __ldg(src + (size_t)p.x * 8 + ch);
        gather_fma8(acc, __int_as_float(p.y), b);
    }
    return acc;
}

// Hops 1,2: half -> half
__global__ void __launch_bounds__(256) spmm_h2h_kernel(
    const uint4* __restrict__ src, uint4* __restrict__ dst, int N)
{
    const int ch  = threadIdx.x & 7;
    const int row = blockIdx.x * 32 + (threadIdx.x >> 3);
    if (row >= N) return;
    Acc8 acc = spmm_row_accum(src, row, ch);
    __half2 h0 = __floats2half2_rn(acc.f[0], acc.f[1]);
    __half2 h1 = __floats2half2_rn(acc.f[2], acc.f[3]);
    __half2 h2 = __floats2half2_rn(acc.f[4], acc.f[5]);
    __half2 h3 = __floats2half2_rn(acc.f[6], acc.f[7]);
    uint4 o;
    o.x = *(uint32_t*)&h0; o.y = *(uint32_t*)&h1;
    o.z = *(uint32_t*)&h2; o.w = *(uint32_t*)&h3;
    dst[(size_t)row * 8 + ch] = o;
}

// Hop 3: half -> float (d_out). Each thread writes two float4.
__global__ void __launch_bounds__(256) spmm_h2f_kernel(
    const uint4* __restrict__ src, float4* __restrict__ dst, int N)
{
    const int ch  = threadIdx.x & 7;
    const int row = blockIdx.x * 32 + (threadIdx.x >> 3);
    if (row >= N) return;
    Acc8 acc = spmm_row_accum(src, row, ch);
    float4 lo = make_float4(acc.f[0], acc.f[1], acc.f[2], acc.f[3]);
    float4 hi = make_float4(acc.f[4], acc.f[5], acc.f[6], acc.f[7]);
    dst[(size_t)row * 16 + ch * 2 + 0] = lo;
    dst[(size_t)row * 16 + ch * 2 + 1] = hi;
}

// ===================== launch ===============================================
// Main stream: memset -> histogram -> scan x3 -> scatter --\
// Side  s2:   transpose -> GEMM ------------------------ join -> spmm x3
extern "C" void kernel_launch(void* const* d_in, const int* in_sizes, int n_in,
                              void* d_out, int out_size)
{
    const void*  adj  = d_in[0];
    const float* vals = (const float*)d_in[1];
    const float* X    = (const float*)d_in[2];
    const float* W    = (const float*)d_in[3];
    const float* bias = (const float*)d_in[4];
    float4*      out  = (float4*)d_out;

    const int E = in_sizes[0] / 2;
    const int N = in_sizes[2] / N_IN;

    uint4* hA = nullptr;
    uint4* hB = nullptr;
    int*   degp = nullptr;
    cudaGetSymbolAddress((void**)&hA, g_hA);
    cudaGetSymbolAddress((void**)&hB, g_hB);
    cudaGetSymbolAddress((void**)&degp, g_deg);

    // One-time host objects (no device memory involved).
    static cudaStream_t s2 = nullptr;
    static cudaEvent_t evFork = nullptr, evJoin = nullptr;
    if (!s2) {
        cudaStreamCreate(&s2);
        cudaEventCreateWithFlags(&evFork, cudaEventDisableTiming);
        cudaEventCreateWithFlags(&evJoin, cudaEventDisableTiming);
    }

    // Fork side branch off stream 0.
    cudaEventRecord(evFork, 0);
    cudaStreamWaitEvent(s2, evFork, 0);

    // Side branch: W transpose -> tf32 GEMM -> hA (fp16)
    transpose_w_kernel<<<(N_IN * N_OUT + 255) / 256, 256, 0, s2>>>(W);
    gemm_tf32_kernel<<<(N + 127) / 128, 256, 0, s2>>>(X, bias, (__half*)hA, N);
    cudaEventRecord(evJoin, s2);

    // Main branch: CSR build (dtype detect folded into hist/scatter blocks)
    cudaMemsetAsync(degp, 0, (size_t)N * sizeof(int), 0);
    const int eb2 = (E + 511) / 512;
    histogram_kernel<<<eb2, 256>>>(adj, E);
    const int NB = (N + SCAN_BS - 1) / SCAN_BS;
    scan1_kernel<<<NB, SCAN_BS>>>(N);
    scan2_kernel<<<1, MAX_SCAN_BLOCKS>>>(NB);
    scan3_kernel<<<(N + 255) / 256, 256>>>(N);
    scatter_kernel<<<eb2, 256>>>(adj, vals, E);

    // Join: SpMM needs both hA (GEMM) and CSR.
    cudaStreamWaitEvent(0, evJoin, 0);

    const int spmm_blocks = (N + 31) / 32;
    spmm_h2h_kernel<<<spmm_blocks, 256>>>(hA, hB, N);
    spmm_h2h_kernel<<<spmm_blocks, 256>>>(hB, hA, N);
    spmm_h2f_kernel<<<spmm_blocks, 256>>>(hA, out, N);
}